// round 11
// baseline (speedup 1.0000x reference)
#include <cuda_runtime.h>
#include <stdint.h>
#include <math.h>

#define SS 256
#define BB 256
#define HH 1024
#define LL 3
#define NCTA 144
#define NTHR 256
#define KC 128                 /* int8 per K-chunk */
#define NCHUNK 16
#define BH (BB*HH)
#define GSTRIDE (NCTA*NTHR)
#define KTOT 2048
#define RSB 144                /* smem row stride bytes (128 data + 16 pad) */
#define OFF_W 18432
#define BUFSZ 36864
#define NSTAGE 3
#define SMEM_DYN (NSTAGE*BUFSZ + 16)
#define QMAX 16256             /* 127*128 */
#define HSC (1.0f/16256.0f)

typedef signed char s8;

// ---------------- device state (static scratch; allocation forbidden) --------
__device__ s8 g_ha1[LL][2][BH];        // h limb1 (x128)
__device__ s8 g_ha0[LL][2][BH];        // h limb0
__device__ s8 g_xa1[2][BH];
__device__ s8 g_xa0[2][BH];
__device__ s8 g_w1[LL][HH][KTOT];      // [l][n][k2]: k2<1024 W_ih (scale wscI), else W_hh (wscH)
__device__ s8 g_w0[LL][HH][KTOT];
__device__ float g_sx[2][BB];          // per-batch-row x scale
__device__ float g_wscI[LL][HH];
__device__ float g_wscH[LL][HH];
__device__ float g_bias[LL][HH];
__device__ int g_part[LL][3][2][BH];   // [l][product][ih/hh] int32 partials
__device__ unsigned g_sync[2];

// ---------------- helpers ----------------------------------------------------
static __device__ __forceinline__ unsigned smem_u32(const void* p) {
    unsigned a;
    asm("{ .reg .u64 t; cvta.to.shared.u64 t, %1; cvt.u32.u64 %0, t; }" : "=r"(a) : "l"(p));
    return a;
}
static __device__ __forceinline__ void cp16(unsigned s, const void* g) {
    asm volatile("cp.async.cg.shared.global [%0], [%1], 16;" :: "r"(s), "l"(g) : "memory");
}
static __device__ __forceinline__ void cp_commit() {
    asm volatile("cp.async.commit_group;" ::: "memory");
}
static __device__ __forceinline__ void cp_wait1() {
    asm volatile("cp.async.wait_group 1;" ::: "memory");
}
static __device__ __forceinline__ void cp_wait0() {
    asm volatile("cp.async.wait_group 0;" ::: "memory");
}
static __device__ __forceinline__ void ldm_x4(unsigned* r, unsigned a) {
    asm volatile("ldmatrix.sync.aligned.m8n8.x4.shared.b16 {%0,%1,%2,%3}, [%4];"
                 : "=r"(r[0]), "=r"(r[1]), "=r"(r[2]), "=r"(r[3]) : "r"(a));
}
static __device__ __forceinline__ void imma(int* c, const unsigned* a, const unsigned* b) {
    asm volatile("mma.sync.aligned.m16n8k32.row.col.s32.s8.s8.s32 "
                 "{%0,%1,%2,%3}, {%4,%5,%6,%7}, {%8,%9}, {%0,%1,%2,%3};"
                 : "+r"(c[0]), "+r"(c[1]), "+r"(c[2]), "+r"(c[3])
                 : "r"(a[0]), "r"(a[1]), "r"(a[2]), "r"(a[3]), "r"(b[0]), "r"(b[1]));
}
static __device__ __forceinline__ unsigned pack4(int b0, int b1, int b2, int b3) {
    return (unsigned)(b0 & 255) | ((unsigned)(b1 & 255) << 8)
         | ((unsigned)(b2 & 255) << 16) | ((unsigned)(b3 & 255) << 24);
}
// 15-bit two-limb quantization: v*inv rounded to |q|<=QMAX, q = q1*128 + q0
static __device__ __forceinline__ void qsplit(float v, float inv, int& q1, int& q0) {
    int q = __float2int_rn(v * inv);
    q = max(-QMAX, min(QMAX, q));
    int a1 = (q >= 0) ? ((q + 64) >> 7) : -(((-q) + 64) >> 7);
    q0 = q - (a1 << 7);
    q1 = a1;
}

// sense-free grid barrier; 144 CTAs co-resident
__device__ __forceinline__ void grid_barrier(unsigned target) {
    __syncthreads();
    __threadfence();
    if (threadIdx.x == 0) {
        unsigned old = atomicAdd(&g_sync[0], 1u);
        if (old == NCTA - 1) {
            atomicExch(&g_sync[0], 0u);
            __threadfence();
            atomicExch(&g_sync[1], target);
        } else {
            while (*((volatile unsigned*)&g_sync[1]) < target) { }
        }
        __threadfence();
    }
    __syncthreads();
}

// quantize rows {2*cta, 2*cta+1} of x_t into slot t&1 with per-row scales (CTA-local)
static __device__ void xsplit_rows(const float* x, int t, int cta, int tid) {
    if (cta >= 128) return;                       // uniform per CTA; no barrier skipped across CTA
    __shared__ float s_red[NTHR];
    const int g = tid >> 7, tl = tid & 127;
    const int row = cta * 2 + g;
    const float* src = x + (size_t)t * BH + (size_t)row * HH + tl * 8;
    float4 v0 = *(const float4*)src;
    float4 v1 = *(const float4*)(src + 4);
    float vv[8] = {v0.x, v0.y, v0.z, v0.w, v1.x, v1.y, v1.z, v1.w};
    float mx = 0.f;
    #pragma unroll
    for (int j = 0; j < 8; j++) mx = fmaxf(mx, fabsf(vv[j]));
    s_red[tid] = mx;
    __syncthreads();
    #pragma unroll
    for (int off = 64; off > 0; off >>= 1) {
        if (tl < off) s_red[tid] = fmaxf(s_red[tid], s_red[tid + off]);
        __syncthreads();
    }
    const float m = fmaxf(s_red[g << 7], 1e-20f);
    const float inv = (float)QMAX / m;
    if (tl == 0) g_sx[t & 1][row] = m * HSC;
    int q1[8], q0[8];
    #pragma unroll
    for (int j = 0; j < 8; j++) qsplit(vv[j], inv, q1[j], q0[j]);
    const size_t off8 = (size_t)row * HH + tl * 8;
    *(uint2*)&g_xa1[t & 1][off8] = make_uint2(pack4(q1[0], q1[1], q1[2], q1[3]),
                                              pack4(q1[4], q1[5], q1[6], q1[7]));
    *(uint2*)&g_xa0[t & 1][off8] = make_uint2(pack4(q0[0], q0[1], q0[2], q0[3]),
                                              pack4(q0[4], q0[5], q0[6], q0[7]));
}

// cp.async: A-limb tile [128][128]B + W-limb tile [128][128]B for chunk c
static __device__ __forceinline__ void issue_loads(
    int c, unsigned sbase, int tid, int m0, int n0,
    const s8* aIn, const s8* aPrv, const s8* wC)
{
    const int ko = (c & 7) * KC;
    const s8* aC = (c < 8) ? aIn : aPrv;
    #pragma unroll
    for (int j = 0; j < 4; j++) {
        int cid = tid + 256 * j;
        int row = cid >> 3, seg = cid & 7;
        cp16(sbase + row * RSB + seg * 16, aC + (size_t)(m0 + row) * HH + ko + seg * 16);
    }
    #pragma unroll
    for (int j = 0; j < 4; j++) {
        int cid = tid + 256 * j;
        int row = cid >> 3, seg = cid & 7;
        cp16(sbase + OFF_W + row * RSB + seg * 16, wC + (size_t)(n0 + row) * KTOT + c * KC + seg * 16);
    }
}

// warp computes its 32x64 sub-tile; 4 k32-steps per 128-int8 chunk
static __device__ __forceinline__ void compute_chunk(
    unsigned sbase, int lane, int wm, int wn, int acc[2][8][4])
{
    const int arow = lane & 15, ak = (lane >> 4) * 16;              // A lane->addr
    const int brow = (lane & 7) + ((lane >> 4) & 1) * 8;            // B lane->addr
    const int bk = ((lane >> 3) & 1) * 16;
    #pragma unroll
    for (int kk = 0; kk < 4; kk++) {
        unsigned a[2][4], b[8][2];
        #pragma unroll
        for (int mb = 0; mb < 2; mb++)
            ldm_x4(a[mb], sbase + (wm + mb * 16 + arow) * RSB + kk * 32 + ak);
        #pragma unroll
        for (int g = 0; g < 4; g++) {
            unsigned r[4];
            ldm_x4(r, sbase + OFF_W + (wn + g * 16 + brow) * RSB + kk * 32 + bk);
            b[2 * g][0] = r[0]; b[2 * g][1] = r[1];       // n-block 0: {k0-15, k16-31}
            b[2 * g + 1][0] = r[2]; b[2 * g + 1][1] = r[3];
        }
        #pragma unroll
        for (int mb = 0; mb < 2; mb++)
            #pragma unroll
            for (int nb = 0; nb < 8; nb++)
                imma(acc[mb][nb], a[mb], b[nb]);
    }
}

static __device__ __forceinline__ void store_partial(
    int* pd, int m0, int n0, int wm, int wn, int lane, int acc[2][8][4])
{
    #pragma unroll
    for (int mb = 0; mb < 2; mb++)
        #pragma unroll
        for (int rh = 0; rh < 2; rh++) {
            const int gm = m0 + wm + mb * 16 + rh * 8 + (lane >> 2);
            #pragma unroll
            for (int nb = 0; nb < 8; nb++) {
                const int gn = n0 + wn + nb * 8 + 2 * (lane & 3);
                *(int2*)(pd + (size_t)gm * HH + gn) =
                    make_int2(acc[mb][nb][rh * 2 + 0], acc[mb][nb][rh * 2 + 1]);
            }
        }
}

// ---------------- persistent kernel ------------------------------------------
__global__ void __launch_bounds__(NTHR, 1) rnn_imma(
    const float* __restrict__ x, const float* __restrict__ h0,
    const float* __restrict__ W_ih, const float* __restrict__ W_hh,
    const float* __restrict__ b_ih, const float* __restrict__ b_hh,
    float* __restrict__ out)
{
    extern __shared__ __align__(16) char dsm[];
    __shared__ float s_wred[NTHR];

    const int tid = threadIdx.x;
    const int lane = tid & 31;
    const int w = tid >> 5;
    const int wm = (w >> 1) * 32;
    const int wn = (w & 1) * 64;
    const int cta = blockIdx.x;
    const int l = cta / 48;
    const int p = (cta / 16) % 3;        // 0: a1*w1(x16384) 1: a1*w0(x128) 2: a0*w1(x128)
    const int tile = cta % 16;
    const int m0 = (tile & 1) * 128;
    const int n0 = (tile >> 1) * 128;

    const unsigned dynu = smem_u32(dsm);

    // ---- prepass 1: per-row W quantization (ih and hh halves separately) ----
    for (int r = cta; r < LL * HH; r += NCTA) {
        const int lr = r >> 10, nr = r & 1023;
        const int hf = tid >> 7, tl = tid & 127;
        const float* src = (hf == 0)
            ? (W_ih + ((size_t)lr * HH + nr) * HH + tl * 8)
            : (W_hh + ((size_t)lr * HH + nr) * HH + tl * 8);
        float4 v0 = *(const float4*)src;
        float4 v1 = *(const float4*)(src + 4);
        float vv[8] = {v0.x, v0.y, v0.z, v0.w, v1.x, v1.y, v1.z, v1.w};
        float mx = 0.f;
        #pragma unroll
        for (int j = 0; j < 8; j++) mx = fmaxf(mx, fabsf(vv[j]));
        s_wred[tid] = mx;
        __syncthreads();
        #pragma unroll
        for (int off = 64; off > 0; off >>= 1) {
            if (tl < off) s_wred[tid] = fmaxf(s_wred[tid], s_wred[tid + off]);
            __syncthreads();
        }
        const float m = fmaxf(s_wred[hf << 7], 1e-20f);
        const float inv = (float)QMAX / m;
        if (tl == 0) {
            if (hf == 0) g_wscI[lr][nr] = m * HSC;
            else         g_wscH[lr][nr] = m * HSC;
        }
        int q1[8], q0[8];
        #pragma unroll
        for (int j = 0; j < 8; j++) qsplit(vv[j], inv, q1[j], q0[j]);
        const size_t o = (size_t)hf * 1024 + tl * 8;
        *(uint2*)&g_w1[lr][nr][o] = make_uint2(pack4(q1[0], q1[1], q1[2], q1[3]),
                                               pack4(q1[4], q1[5], q1[6], q1[7]));
        *(uint2*)&g_w0[lr][nr][o] = make_uint2(pack4(q0[0], q0[1], q0[2], q0[3]),
                                               pack4(q0[4], q0[5], q0[6], q0[7]));
        __syncthreads();
    }
    // ---- prepass 2: h0 (parity 1), bias, x0 ---------------------------------
    for (int idx = cta * NTHR + tid; idx < LL * BH / 4; idx += GSTRIDE) {
        const int l2 = idx / (BH / 4);
        const int i = (idx - l2 * (BH / 4)) * 4;
        float4 v = *(const float4*)(h0 + (size_t)l2 * BH + i);
        int q1[4], q0[4];
        qsplit(v.x, (float)QMAX, q1[0], q0[0]);
        qsplit(v.y, (float)QMAX, q1[1], q0[1]);
        qsplit(v.z, (float)QMAX, q1[2], q0[2]);
        qsplit(v.w, (float)QMAX, q1[3], q0[3]);
        *(unsigned*)&g_ha1[l2][1][i] = pack4(q1[0], q1[1], q1[2], q1[3]);
        *(unsigned*)&g_ha0[l2][1][i] = pack4(q0[0], q0[1], q0[2], q0[3]);
    }
    for (int idx = cta * NTHR + tid; idx < LL * HH; idx += GSTRIDE)
        ((float*)g_bias)[idx] = b_ih[idx] + b_hh[idx];
    xsplit_rows(x, 0, cta, tid);

    grid_barrier(1u);
    unsigned bt = 2;

    const s8* wC = (p == 1) ? &g_w0[l][0][0] : &g_w1[l][0][0];

    for (int d = 0; d < SS + LL - 1; d++) {
        const int t = d - l;
        if (t >= 0 && t < SS) {
            const s8* aIn = (p == 2)
                ? ((l == 0) ? g_xa0[t & 1] : g_ha0[l - 1][t & 1])
                : ((l == 0) ? g_xa1[t & 1] : g_ha1[l - 1][t & 1]);
            const s8* aPrv = (p == 2) ? g_ha0[l][(t & 1) ^ 1] : g_ha1[l][(t & 1) ^ 1];

            int acc[2][8][4];
            #pragma unroll
            for (int a = 0; a < 2; a++)
                #pragma unroll
                for (int b = 0; b < 8; b++)
                    #pragma unroll
                    for (int cc = 0; cc < 4; cc++) acc[a][b][cc] = 0;

            // 3-stage cp.async ring, one barrier per chunk; ih = chunks 0-7, hh = 8-15
            issue_loads(0, dynu + 0 * BUFSZ, tid, m0, n0, aIn, aPrv, wC);
            cp_commit();
            issue_loads(1, dynu + 1 * BUFSZ, tid, m0, n0, aIn, aPrv, wC);
            cp_commit();
            int bufc = 0;
            for (int c = 0; c < NCHUNK; c++) {
                if (c == NCHUNK - 1) cp_wait0(); else cp_wait1();
                __syncthreads();
                if (c + 2 < NCHUNK) {
                    int bufn = bufc + 2 - ((bufc + 2 >= NSTAGE) ? NSTAGE : 0);
                    issue_loads(c + 2, dynu + bufn * BUFSZ, tid, m0, n0, aIn, aPrv, wC);
                    cp_commit();
                }
                compute_chunk(dynu + bufc * BUFSZ, lane, wm, wn, acc);
                if (c == 7) {   // flush ih partial, restart accumulation for hh
                    store_partial(&g_part[l][p][0][0], m0, n0, wm, wn, lane, acc);
                    #pragma unroll
                    for (int a = 0; a < 2; a++)
                        #pragma unroll
                        for (int b = 0; b < 8; b++)
                            #pragma unroll
                            for (int cc = 0; cc < 4; cc++) acc[a][b][cc] = 0;
                }
                if (++bufc == NSTAGE) bufc = 0;
            }
            store_partial(&g_part[l][p][1][0], m0, n0, wm, wn, lane, acc);
        }
        grid_barrier(bt++);   // all partials of diagonal d visible

        // ---- combine: 6 int32 partials -> pre-act -> tanh -> limbs + outputs -
        for (int v = cta * NTHR + tid; v < 3 * BH / 4; v += GSTRIDE) {
            const int s = v >> 16;              // BH/4 = 65536 per layer slot
            const int tt = d - s;
            if (tt < 0 || tt >= SS) continue;
            const int i = (v & 65535) * 4;
            const int m = i >> 10, nn = i & 1023;
            const int4 A1 = *(const int4*)&g_part[s][0][0][i];
            const int4 B1 = *(const int4*)&g_part[s][1][0][i];
            const int4 C1 = *(const int4*)&g_part[s][2][0][i];
            const int4 A2 = *(const int4*)&g_part[s][0][1][i];
            const int4 B2 = *(const int4*)&g_part[s][1][1][i];
            const int4 C2 = *(const int4*)&g_part[s][2][1][i];
            const float4 swI = *(const float4*)&g_wscI[s][nn];
            const float4 swH = *(const float4*)&g_wscH[s][nn];
            const float4 bv = *(const float4*)&g_bias[s][nn];
            const float sAi = (s == 0) ? g_sx[tt & 1][m] : HSC;
            float f[4];
            {
                const int p1[4] = {A1.x, A1.y, A1.z, A1.w};
                const int p2[4] = {B1.x, B1.y, B1.z, B1.w};
                const int p3[4] = {C1.x, C1.y, C1.z, C1.w};
                const int q1[4] = {A2.x, A2.y, A2.z, A2.w};
                const int q2[4] = {B2.x, B2.y, B2.z, B2.w};
                const int q3[4] = {C2.x, C2.y, C2.z, C2.w};
                const float swi[4] = {swI.x, swI.y, swI.z, swI.w};
                const float swh[4] = {swH.x, swH.y, swH.z, swH.w};
                const float bb[4] = {bv.x, bv.y, bv.z, bv.w};
                #pragma unroll
                for (int j = 0; j < 4; j++) {
                    float preI = sAi * swi[j] *
                        (16384.f * (float)p1[j] + 128.f * (float)(p2[j] + p3[j]));
                    float preH = HSC * swh[j] *
                        (16384.f * (float)q1[j] + 128.f * (float)(q2[j] + q3[j]));
                    f[j] = tanhf(preI + preH + bb[j]);
                }
            }
            if (s == LL - 1)
                *(float4*)(out + (size_t)tt * BH + i) = make_float4(f[0], f[1], f[2], f[3]);
            if (tt == SS - 1)
                *(float4*)(out + (size_t)SS * BH + (size_t)s * BH + i) =
                    make_float4(f[0], f[1], f[2], f[3]);
            int q1v[4], q0v[4];
            #pragma unroll
            for (int j = 0; j < 4; j++) qsplit(f[j], (float)QMAX, q1v[j], q0v[j]);
            *(unsigned*)&g_ha1[s][tt & 1][i] = pack4(q1v[0], q1v[1], q1v[2], q1v[3]);
            *(unsigned*)&g_ha0[s][tt & 1][i] = pack4(q0v[0], q0v[1], q0v[2], q0v[3]);
        }
        // split x_{d+1} (per-row scale, CTA-local reduction; no extra barrier)
        if (d + 1 < SS) xsplit_rows(x, d + 1, cta, tid);
        grid_barrier(bt++);   // h/x limbs ready for diagonal d+1
    }
}

extern "C" void kernel_launch(void* const* d_in, const int* in_sizes, int n_in,
                              void* d_out, int out_size) {
    const float* x    = (const float*)d_in[0];
    const float* h0   = (const float*)d_in[1];
    const float* W_ih = (const float*)d_in[2];
    const float* W_hh = (const float*)d_in[3];
    const float* b_ih = (const float*)d_in[4];
    const float* b_hh = (const float*)d_in[5];
    float* out = (float*)d_out;

    cudaFuncSetAttribute(rnn_imma, cudaFuncAttributeMaxDynamicSharedMemorySize, SMEM_DYN);
    void* sp = nullptr;
    cudaGetSymbolAddress(&sp, g_sync);
    cudaMemsetAsync(sp, 0, sizeof(unsigned) * 2);
    rnn_imma<<<NCTA, NTHR, SMEM_DYN>>>(x, h0, W_ih, W_hh, b_ih, b_hh, out);
}

// round 13
// speedup vs baseline: 3.0925x; 3.0925x over previous
#include <cuda_runtime.h>
#include <cuda_bf16.h>
#include <stdint.h>
#include <math.h>

#define SS 256
#define BB 256
#define HH 1024
#define LL 3
#define NCTA 144
#define NTHR 256
#define KC 64
#define NCHUNK 32
#define BH (BB*HH)
#define GSTRIDE (NCTA*NTHR)
#define KTOT 2048
#define RSB 144
#define OFF_W 18432
#define BUFSZ 36864
#define NSTAGE 3
#define SMEM_DYN (NSTAGE*BUFSZ + 16)
#define NFLAG 48

typedef unsigned short ush;

// ---------------- device state (static scratch; allocation forbidden) --------
__device__ ush g_h_hi[LL][2][BH];
__device__ ush g_h_lo[LL][2][BH];
__device__ ush g_x_hi[2][BH];
__device__ ush g_x_lo[2][BH];
__device__ ush g_w_hi[LL][HH][KTOT];     // [l][n][k2]: k2<1024 W_ih, else W_hh
__device__ ush g_w_lo[LL][HH][KTOT];
__device__ float g_part1[LL][BH];        // P1 = Ah*Wh (fp32)
__device__ ush g_part2[LL][BH];          // P2 = Al*Wh (bf16)
__device__ ush g_part3[LL][BH];          // P3 = Ah*Wl (bf16)
__device__ float g_bias[LL][HH];
__device__ unsigned g_sync[2 + NFLAG];   // [0]=count [1]=gen [2..]=per-(l,tile) flags

// ---------------- helpers ----------------------------------------------------
static __device__ __forceinline__ unsigned smem_u32(const void* p) {
    unsigned a;
    asm("{ .reg .u64 t; cvta.to.shared.u64 t, %1; cvt.u32.u64 %0, t; }" : "=r"(a) : "l"(p));
    return a;
}
static __device__ __forceinline__ ush f2bf(float f) {
    ush r; asm("cvt.rn.bf16.f32 %0, %1;" : "=h"(r) : "f"(f)); return r;
}
static __device__ __forceinline__ float bf2f(ush h) {
    return __uint_as_float(((unsigned)h) << 16);
}
static __device__ __forceinline__ void split2(float f, ush& hi, ush& lo) {
    unsigned u = __float_as_uint(f) & 0xFFFF0000u;
    hi = (ush)(u >> 16);
    lo = f2bf(f - __uint_as_float(u));
}
static __device__ __forceinline__ float ftanh(float p) {
    float xc = fminf(fmaxf(p, -15.f), 15.f);
    float e = __expf(2.f * xc);
    return __fdividef(e - 1.f, e + 1.f);
}
static __device__ __forceinline__ void cp16(unsigned s, const void* g) {
    asm volatile("cp.async.cg.shared.global [%0], [%1], 16;" :: "r"(s), "l"(g) : "memory");
}
static __device__ __forceinline__ void cp_commit() {
    asm volatile("cp.async.commit_group;" ::: "memory");
}
static __device__ __forceinline__ void cp_wait1() {
    asm volatile("cp.async.wait_group 1;" ::: "memory");
}
static __device__ __forceinline__ void cp_wait0() {
    asm volatile("cp.async.wait_group 0;" ::: "memory");
}
static __device__ __forceinline__ void ldm_x4(unsigned* r, unsigned a) {
    asm volatile("ldmatrix.sync.aligned.m8n8.x4.shared.b16 {%0,%1,%2,%3}, [%4];"
                 : "=r"(r[0]), "=r"(r[1]), "=r"(r[2]), "=r"(r[3]) : "r"(a));
}
static __device__ __forceinline__ void mma16816(float* c, const unsigned* a, const unsigned* b) {
    asm volatile("mma.sync.aligned.m16n8k16.row.col.f32.bf16.bf16.f32 "
                 "{%0,%1,%2,%3}, {%4,%5,%6,%7}, {%8,%9}, {%0,%1,%2,%3};"
                 : "+f"(c[0]), "+f"(c[1]), "+f"(c[2]), "+f"(c[3])
                 : "r"(a[0]), "r"(a[1]), "r"(a[2]), "r"(a[3]), "r"(b[0]), "r"(b[1]));
}

// sense-free grid barrier; 144 CTAs co-resident
__device__ __forceinline__ void grid_barrier(unsigned target) {
    __syncthreads();
    __threadfence();
    if (threadIdx.x == 0) {
        unsigned old = atomicAdd(&g_sync[0], 1u);
        if (old == NCTA - 1) {
            atomicExch(&g_sync[0], 0u);
            __threadfence();
            atomicExch(&g_sync[1], target);
        } else {
            while (*((volatile unsigned*)&g_sync[1]) < target) { }
        }
        __threadfence();
    }
    __syncthreads();
}

static __device__ __forceinline__ void issue_loads(
    int c, unsigned sbase, int tid, int m0, int n0,
    const ush* inpC, const ush* prvC, const ush* wC)
{
    const int ko = (c & 15) * KC;
    const ush* aC = (c < 16) ? inpC : prvC;
    #pragma unroll
    for (int j = 0; j < 4; j++) {
        int cid = tid + 256 * j;
        int row = cid >> 3, seg = cid & 7;
        cp16(sbase + row * RSB + seg * 16, aC + (size_t)(m0 + row) * HH + ko + seg * 8);
    }
    #pragma unroll
    for (int j = 0; j < 4; j++) {
        int cid = tid + 256 * j;
        int row = cid >> 3, seg = cid & 7;
        cp16(sbase + OFF_W + row * RSB + seg * 16, wC + (size_t)(n0 + row) * KTOT + c * KC + seg * 8);
    }
}

static __device__ __forceinline__ void compute_chunk(
    unsigned sbase, int lane, int wm, int wn, float acc[2][8][4])
{
    const int arow = lane & 15, akoff = (lane >> 4) * 8;
    #pragma unroll
    for (int kk = 0; kk < 4; kk++) {
        unsigned a[2][4], b[8][2];
        #pragma unroll
        for (int mb = 0; mb < 2; mb++)
            ldm_x4(a[mb], sbase + (wm + mb * 16 + arow) * RSB + (kk * 16 + akoff) * 2);
        #pragma unroll
        for (int g = 0; g < 4; g++) {
            unsigned r[4];
            ldm_x4(r, sbase + OFF_W + (wn + g * 16 + arow) * RSB + (kk * 16 + akoff) * 2);
            b[2 * g][0] = r[0]; b[2 * g][1] = r[2];
            b[2 * g + 1][0] = r[1]; b[2 * g + 1][1] = r[3];
        }
        #pragma unroll
        for (int mb = 0; mb < 2; mb++)
            #pragma unroll
            for (int nb = 0; nb < 8; nb++)
                mma16816(acc[mb][nb], a[mb], b[nb]);
    }
}

// ---------------- persistent kernel ------------------------------------------
__global__ void __launch_bounds__(NTHR, 1) rnn_mma(
    const float* __restrict__ x, const float* __restrict__ h0,
    const float* __restrict__ W_ih, const float* __restrict__ W_hh,
    const float* __restrict__ b_ih, const float* __restrict__ b_hh,
    float* __restrict__ out)
{
    extern __shared__ __align__(16) char dsm[];

    const int tid = threadIdx.x;
    const int lane = tid & 31;
    const int w = tid >> 5;
    const int wm = (w >> 1) * 32;
    const int wn = (w & 1) * 64;
    const int cta = blockIdx.x;
    const int l = cta / 48;
    const int p = (cta / 16) % 3;        // 0: Ah*Wh(fp32) 1: Al*Wh(bf16) 2: Ah*Wl(bf16)
    const int tile = cta % 16;
    const int m0 = (tile & 1) * 128;
    const int n0 = (tile >> 1) * 128;
    volatile unsigned* flag = &g_sync[2 + l * 16 + tile];

    const unsigned dynu = smem_u32(dsm);

    // ---- prepass: split W / h0 / x0, bias sums ------------------------------
    for (int idx = cta * NTHR + tid; idx < LL * HH * KTOT; idx += GSTRIDE) {
        int l2 = idx >> 21;
        int rem = idx & ((1 << 21) - 1);
        int n = rem >> 11;
        int k2 = rem & (KTOT - 1);
        float f = (k2 < HH) ? W_ih[((size_t)l2 * HH + n) * HH + k2]
                            : W_hh[((size_t)l2 * HH + n) * HH + (k2 - HH)];
        split2(f, ((ush*)g_w_hi)[idx], ((ush*)g_w_lo)[idx]);
    }
    for (int idx = cta * NTHR + tid; idx < LL * BH; idx += GSTRIDE) {
        int l2 = idx >> 18;
        int i = idx & (BH - 1);
        split2(h0[idx], g_h_hi[l2][1][i], g_h_lo[l2][1][i]);
    }
    for (int idx = cta * NTHR + tid; idx < BH; idx += GSTRIDE)
        split2(x[idx], g_x_hi[0][idx], g_x_lo[0][idx]);
    for (int idx = cta * NTHR + tid; idx < LL * HH; idx += GSTRIDE)
        ((float*)g_bias)[idx] = b_ih[idx] + b_hh[idx];

    grid_barrier(1u);
    unsigned bt = 2, fcnt = 0;

    const ush* wC = (p == 2) ? &g_w_lo[l][0][0] : &g_w_hi[l][0][0];

    for (int d = 0; d < SS + LL - 1; d++) {
        const int t = d - l;
        if (t >= 0 && t < SS) {
            const ush* inpC;
            const ush* prvC;
            if (p == 1) {
                inpC = (l == 0) ? g_x_lo[t & 1] : g_h_lo[l - 1][t & 1];
                prvC = g_h_lo[l][(t & 1) ^ 1];
            } else {
                inpC = (l == 0) ? g_x_hi[t & 1] : g_h_hi[l - 1][t & 1];
                prvC = g_h_hi[l][(t & 1) ^ 1];
            }

            float acc[2][8][4];
            #pragma unroll
            for (int a = 0; a < 2; a++)
                #pragma unroll
                for (int b = 0; b < 8; b++)
                    #pragma unroll
                    for (int cc = 0; cc < 4; cc++) acc[a][b][cc] = 0.f;

            // 3-stage cp.async ring, one CTA barrier per chunk
            issue_loads(0, dynu + 0 * BUFSZ, tid, m0, n0, inpC, prvC, wC);
            cp_commit();
            issue_loads(1, dynu + 1 * BUFSZ, tid, m0, n0, inpC, prvC, wC);
            cp_commit();
            int bufc = 0;
            for (int c = 0; c < NCHUNK; c++) {
                if (c == NCHUNK - 1) cp_wait0(); else cp_wait1();
                __syncthreads();
                if (c + 2 < NCHUNK) {
                    int bufn = bufc + 2 - ((bufc + 2 >= NSTAGE) ? NSTAGE : 0);
                    issue_loads(c + 2, dynu + bufn * BUFSZ, tid, m0, n0, inpC, prvC, wC);
                    cp_commit();
                }
                compute_chunk(dynu + bufc * BUFSZ, lane, wm, wn, acc);
                if (++bufc == NSTAGE) bufc = 0;
            }

            // ---- publish partial tile ---------------------------------------
            if (p == 0) {
                float* pd = &g_part1[l][0];
                #pragma unroll
                for (int mb = 0; mb < 2; mb++)
                    #pragma unroll
                    for (int rh = 0; rh < 2; rh++) {
                        const int gm = m0 + wm + mb * 16 + rh * 8 + (lane >> 2);
                        #pragma unroll
                        for (int nb = 0; nb < 8; nb++) {
                            const int gn = n0 + wn + nb * 8 + 2 * (lane & 3);
                            *(float2*)(pd + (size_t)gm * HH + gn) =
                                make_float2(acc[mb][nb][rh * 2 + 0], acc[mb][nb][rh * 2 + 1]);
                        }
                    }
            } else {
                ush* pd = (p == 1) ? &g_part2[l][0] : &g_part3[l][0];
                #pragma unroll
                for (int mb = 0; mb < 2; mb++)
                    #pragma unroll
                    for (int rh = 0; rh < 2; rh++) {
                        const int gm = m0 + wm + mb * 16 + rh * 8 + (lane >> 2);
                        #pragma unroll
                        for (int nb = 0; nb < 8; nb++) {
                            const int gn = n0 + wn + nb * 8 + 2 * (lane & 3);
                            unsigned v = (unsigned)f2bf(acc[mb][nb][rh * 2 + 0])
                                       | ((unsigned)f2bf(acc[mb][nb][rh * 2 + 1]) << 16);
                            *(unsigned*)(pd + (size_t)gm * HH + gn) = v;
                        }
                    }
            }
            __threadfence();              // release partial stores
            __syncthreads();
            if (tid == 0) atomicAdd((unsigned*)flag, 1u);
            fcnt++;

            // ---- wait siblings, combine own third of this tile --------------
            if (tid == 0) {
                const unsigned tgt = 3u * fcnt;
                while (*flag < tgt) { }
            }
            __syncthreads();
            __threadfence();              // acquire: fresh partials

            {
                const int q0 = (p * 4096) / 3;
                const int q1 = ((p + 1) * 4096) / 3;
                float* ybase = out + (size_t)t * BH;
                float* hbase = out + (size_t)SS * BH + (size_t)l * BH;
                ush* hiB = g_h_hi[l][t & 1];
                ush* loB = g_h_lo[l][t & 1];
                const bool wy = (l == LL - 1);
                const bool whn = (t == SS - 1);
                for (int q = q0 + tid; q < q1; q += NTHR) {
                    const int gm = m0 + (q >> 5);
                    const int gn = n0 + ((q & 31) << 2);
                    const size_t i = (size_t)gm * HH + gn;
                    const float4 P1 = *(const float4*)&g_part1[l][i];
                    const uint2 u2 = *(const uint2*)&g_part2[l][i];
                    const uint2 u3 = *(const uint2*)&g_part3[l][i];
                    const float4 bv = *(const float4*)&g_bias[l][gn];
                    float f[4];
                    f[0] = ftanh(P1.x + bf2f((ush)(u2.x & 0xFFFF)) + bf2f((ush)(u3.x & 0xFFFF)) + bv.x);
                    f[1] = ftanh(P1.y + bf2f((ush)(u2.x >> 16))    + bf2f((ush)(u3.x >> 16))    + bv.y);
                    f[2] = ftanh(P1.z + bf2f((ush)(u2.y & 0xFFFF)) + bf2f((ush)(u3.y & 0xFFFF)) + bv.z);
                    f[3] = ftanh(P1.w + bf2f((ush)(u2.y >> 16))    + bf2f((ush)(u3.y >> 16))    + bv.w);
                    ush hu[4], lu[4];
                    #pragma unroll
                    for (int j = 0; j < 4; j++) split2(f[j], hu[j], lu[j]);
                    *(uint2*)&hiB[i] = make_uint2((unsigned)hu[0] | ((unsigned)hu[1] << 16),
                                                  (unsigned)hu[2] | ((unsigned)hu[3] << 16));
                    *(uint2*)&loB[i] = make_uint2((unsigned)lu[0] | ((unsigned)lu[1] << 16),
                                                  (unsigned)lu[2] | ((unsigned)lu[3] << 16));
                    if (wy)  *(float4*)(ybase + i) = make_float4(f[0], f[1], f[2], f[3]);
                    if (whn) *(float4*)(hbase + i) = make_float4(f[0], f[1], f[2], f[3]);
                }
            }
        }
        // split x_{d+1} into the other ring slot
        const int tn = d + 1;
        if (tn < SS) {
            const int sl = tn & 1;
            for (int i = cta * NTHR + tid; i < BH; i += GSTRIDE)
                split2(x[(size_t)tn * BH + i], g_x_hi[sl][i], g_x_lo[sl][i]);
        }
        grid_barrier(bt++);   // h/x ready for diagonal d+1
    }
}

extern "C" void kernel_launch(void* const* d_in, const int* in_sizes, int n_in,
                              void* d_out, int out_size) {
    const float* x    = (const float*)d_in[0];
    const float* h0   = (const float*)d_in[1];
    const float* W_ih = (const float*)d_in[2];
    const float* W_hh = (const float*)d_in[3];
    const float* b_ih = (const float*)d_in[4];
    const float* b_hh = (const float*)d_in[5];
    float* out = (float*)d_out;

    cudaFuncSetAttribute(rnn_mma, cudaFuncAttributeMaxDynamicSharedMemorySize, SMEM_DYN);
    void* sp = nullptr;
    cudaGetSymbolAddress(&sp, g_sync);
    cudaMemsetAsync(sp, 0, sizeof(unsigned) * (2 + NFLAG));
    rnn_mma<<<NCTA, NTHR, SMEM_DYN>>>(x, h0, W_ih, W_hh, b_ih, b_hh, out);
}

// round 15
// speedup vs baseline: 3.0951x; 1.0008x over previous
#include <cuda_runtime.h>
#include <cuda_bf16.h>
#include <stdint.h>
#include <math.h>

#define SS 256
#define BB 256
#define HH 1024
#define LL 3
#define NCTA 288
#define NTHR 128
#define KC 64
#define NCHUNK 32
#define BH (BB*HH)
#define GSTRIDE (NCTA*NTHR)
#define KTOT 2048
#define RSB 144                /* 64 k * 2B + 16B pad */
#define OFF_W 9216             /* A: 64 rows * 144B */
#define BUFSZ 27648            /* + W: 128 rows * 144B */
#define NSTAGE 3
#define SMEM_DYN (NSTAGE*BUFSZ + 16)   /* 82960 B -> 2 CTAs/SM guaranteed */

typedef unsigned short ush;

// ---------------- device state (static scratch; allocation forbidden) --------
__device__ ush g_h_hi[LL][2][BH];
__device__ ush g_h_lo[LL][2][BH];
__device__ ush g_x_hi[2][BH];
__device__ ush g_x_lo[2][BH];
__device__ ush g_w_hi[LL][HH][KTOT];   // [l][n][k2]: k2<1024 W_ih, else W_hh
__device__ ush g_w_lo[LL][HH][KTOT];
__device__ float g_part[LL][3][BH];    // per-stage per-product fp32 partials
__device__ float g_bias[LL][HH];
__device__ unsigned g_sync[2];

// ---------------- helpers ----------------------------------------------------
static __device__ __forceinline__ unsigned smem_u32(const void* p) {
    unsigned a;
    asm("{ .reg .u64 t; cvta.to.shared.u64 t, %1; cvt.u32.u64 %0, t; }" : "=r"(a) : "l"(p));
    return a;
}
static __device__ __forceinline__ ush f2bf(float f) {
    ush r; asm("cvt.rn.bf16.f32 %0, %1;" : "=h"(r) : "f"(f)); return r;
}
static __device__ __forceinline__ void split2(float f, ush& hi, ush& lo) {
    unsigned u = __float_as_uint(f) & 0xFFFF0000u;
    hi = (ush)(u >> 16);
    lo = f2bf(f - __uint_as_float(u));
}
static __device__ __forceinline__ float ftanh(float p) {
    float xc = fminf(fmaxf(p, -15.f), 15.f);
    float e = __expf(2.f * xc);
    return __fdividef(e - 1.f, e + 1.f);
}
static __device__ __forceinline__ void cp16(unsigned s, const void* g) {
    asm volatile("cp.async.cg.shared.global [%0], [%1], 16;" :: "r"(s), "l"(g) : "memory");
}
static __device__ __forceinline__ void cp_commit() {
    asm volatile("cp.async.commit_group;" ::: "memory");
}
static __device__ __forceinline__ void cp_wait1() {
    asm volatile("cp.async.wait_group 1;" ::: "memory");
}
static __device__ __forceinline__ void cp_wait0() {
    asm volatile("cp.async.wait_group 0;" ::: "memory");
}
static __device__ __forceinline__ void ldm_x4(unsigned* r, unsigned a) {
    asm volatile("ldmatrix.sync.aligned.m8n8.x4.shared.b16 {%0,%1,%2,%3}, [%4];"
                 : "=r"(r[0]), "=r"(r[1]), "=r"(r[2]), "=r"(r[3]) : "r"(a));
}
static __device__ __forceinline__ void mma16816(float* c, const unsigned* a, const unsigned* b) {
    asm volatile("mma.sync.aligned.m16n8k16.row.col.f32.bf16.bf16.f32 "
                 "{%0,%1,%2,%3}, {%4,%5,%6,%7}, {%8,%9}, {%0,%1,%2,%3};"
                 : "+f"(c[0]), "+f"(c[1]), "+f"(c[2]), "+f"(c[3])
                 : "r"(a[0]), "r"(a[1]), "r"(a[2]), "r"(a[3]), "r"(b[0]), "r"(b[1]));
}

// sense-free grid barrier; 288 CTAs co-resident (2/SM on 144 of 148 SMs:
// smem 83KB/CTA -> exactly 2 fit in 228KB; regs/threads far under limits)
__device__ __forceinline__ void grid_barrier(unsigned target) {
    __syncthreads();
    __threadfence();
    if (threadIdx.x == 0) {
        unsigned old = atomicAdd(&g_sync[0], 1u);
        if (old == NCTA - 1) {
            atomicExch(&g_sync[0], 0u);
            __threadfence();
            atomicExch(&g_sync[1], target);
        } else {
            while (*((volatile unsigned*)&g_sync[1]) < target) { }
        }
        __threadfence();
    }
    __syncthreads();
}

// cp.async for chunk c: A tile [64][64] halves + W tile [128][64] halves
static __device__ __forceinline__ void issue_loads(
    int c, unsigned sbase, int tid, int m0, int n0,
    const ush* inpC, const ush* prvC, const ush* wC)
{
    const int ko = (c & 15) * KC;
    const ush* aC = (c < 16) ? inpC : prvC;
    #pragma unroll
    for (int j = 0; j < 4; j++) {                 // A: 512 16B chunks
        int cid = tid + 128 * j;
        int row = cid >> 3, seg = cid & 7;
        cp16(sbase + row * RSB + seg * 16, aC + (size_t)(m0 + row) * HH + ko + seg * 8);
    }
    #pragma unroll
    for (int j = 0; j < 8; j++) {                 // W: 1024 16B chunks
        int cid = tid + 128 * j;
        int row = cid >> 3, seg = cid & 7;
        cp16(sbase + OFF_W + row * RSB + seg * 16, wC + (size_t)(n0 + row) * KTOT + c * KC + seg * 8);
    }
}

// warp computes its 32x64 sub-tile of the 64x128 CTA tile over one 64-K chunk
static __device__ __forceinline__ void compute_chunk(
    unsigned sbase, int lane, int wm, int wn, float acc[2][8][4])
{
    const int arow = lane & 15, akoff = (lane >> 4) * 8;
    #pragma unroll
    for (int kk = 0; kk < 4; kk++) {
        unsigned a[2][4], b[8][2];
        #pragma unroll
        for (int mb = 0; mb < 2; mb++)
            ldm_x4(a[mb], sbase + (wm + mb * 16 + arow) * RSB + (kk * 16 + akoff) * 2);
        #pragma unroll
        for (int g = 0; g < 4; g++) {
            // non-trans ldmatrix on W[n][k] -> col-major B frag:
            // r0 = n-blk0 k-lo, r1 = n-blk1 k-lo, r2 = n-blk0 k-hi, r3 = n-blk1 k-hi
            unsigned r[4];
            ldm_x4(r, sbase + OFF_W + (wn + g * 16 + arow) * RSB + (kk * 16 + akoff) * 2);
            b[2 * g][0] = r[0]; b[2 * g][1] = r[2];
            b[2 * g + 1][0] = r[1]; b[2 * g + 1][1] = r[3];
        }
        #pragma unroll
        for (int mb = 0; mb < 2; mb++)
            #pragma unroll
            for (int nb = 0; nb < 8; nb++)
                mma16816(acc[mb][nb], a[mb], b[nb]);
    }
}

// ---------------- persistent kernel ------------------------------------------
__global__ void __launch_bounds__(NTHR) rnn_mma(
    const float* __restrict__ x, const float* __restrict__ h0,
    const float* __restrict__ W_ih, const float* __restrict__ W_hh,
    const float* __restrict__ b_ih, const float* __restrict__ b_hh,
    float* __restrict__ out)
{
    extern __shared__ __align__(16) char dsm[];

    const int tid = threadIdx.x;
    const int lane = tid & 31;
    const int w = tid >> 5;              // 4 warps
    const int wm = (w >> 1) * 32;        // 2 warp-rows of the 64-row tile
    const int wn = (w & 1) * 64;         // 2 warp-cols of the 128-col tile
    const int cta = blockIdx.x;
    const int l = cta / 96;              // layer 0..2
    const int p = (cta / 32) % 3;        // 0: Ah*Wh 1: Al*Wh 2: Ah*Wl
    const int tile = cta % 32;           // 4 m-tiles x 8 n-tiles
    const int m0 = (tile & 3) * 64;
    const int n0 = (tile >> 2) * 128;

    const unsigned dynu = smem_u32(dsm);

    // ---- prepass: split W / h0 / x0, bias sums ------------------------------
    for (int idx = cta * NTHR + tid; idx < LL * HH * KTOT; idx += GSTRIDE) {
        int l2 = idx >> 21;
        int rem = idx & ((1 << 21) - 1);
        int n = rem >> 11;
        int k2 = rem & (KTOT - 1);
        float f = (k2 < HH) ? W_ih[((size_t)l2 * HH + n) * HH + k2]
                            : W_hh[((size_t)l2 * HH + n) * HH + (k2 - HH)];
        split2(f, ((ush*)g_w_hi)[idx], ((ush*)g_w_lo)[idx]);
    }
    for (int idx = cta * NTHR + tid; idx < LL * BH; idx += GSTRIDE) {
        int l2 = idx >> 18;
        int i = idx & (BH - 1);
        split2(h0[idx], g_h_hi[l2][1][i], g_h_lo[l2][1][i]);
    }
    for (int idx = cta * NTHR + tid; idx < BH; idx += GSTRIDE)
        split2(x[idx], g_x_hi[0][idx], g_x_lo[0][idx]);
    for (int idx = cta * NTHR + tid; idx < LL * HH; idx += GSTRIDE)
        ((float*)g_bias)[idx] = b_ih[idx] + b_hh[idx];

    grid_barrier(1u);
    unsigned bt = 2;

    const ush* wC = (p == 2) ? &g_w_lo[l][0][0] : &g_w_hi[l][0][0];

    for (int d = 0; d < SS + LL - 1; d++) {
        const int t = d - l;
        if (t >= 0 && t < SS) {
            const ush* inpC;
            const ush* prvC;
            if (p == 1) {   // A = lo component
                inpC = (l == 0) ? g_x_lo[t & 1] : g_h_lo[l - 1][t & 1];
                prvC = g_h_lo[l][(t & 1) ^ 1];
            } else {        // A = hi component
                inpC = (l == 0) ? g_x_hi[t & 1] : g_h_hi[l - 1][t & 1];
                prvC = g_h_hi[l][(t & 1) ^ 1];
            }

            float acc[2][8][4];
            #pragma unroll
            for (int a = 0; a < 2; a++)
                #pragma unroll
                for (int b = 0; b < 8; b++)
                    #pragma unroll
                    for (int cc = 0; cc < 4; cc++) acc[a][b][cc] = 0.f;

            // 3-stage cp.async ring, one barrier per chunk (R6/R10-proven)
            issue_loads(0, dynu + 0 * BUFSZ, tid, m0, n0, inpC, prvC, wC);
            cp_commit();
            issue_loads(1, dynu + 1 * BUFSZ, tid, m0, n0, inpC, prvC, wC);
            cp_commit();
            int bufc = 0;
            for (int c = 0; c < NCHUNK; c++) {
                if (c == NCHUNK - 1) cp_wait0(); else cp_wait1();
                __syncthreads();
                if (c + 2 < NCHUNK) {
                    int bufn = bufc + 2 - ((bufc + 2 >= NSTAGE) ? NSTAGE : 0);
                    issue_loads(c + 2, dynu + bufn * BUFSZ, tid, m0, n0, inpC, prvC, wC);
                    cp_commit();
                }
                compute_chunk(dynu + bufc * BUFSZ, lane, wm, wn, acc);
                if (++bufc == NSTAGE) bufc = 0;
            }

            // write fp32 partial tile to global scratch
            float* pd = &g_part[l][p][0];
            #pragma unroll
            for (int mb = 0; mb < 2; mb++) {
                #pragma unroll
                for (int rh = 0; rh < 2; rh++) {
                    const int gm = m0 + wm + mb * 16 + rh * 8 + (lane >> 2);
                    #pragma unroll
                    for (int nb = 0; nb < 8; nb++) {
                        const int gn = n0 + wn + nb * 8 + 2 * (lane & 3);
                        *(float2*)(pd + (size_t)gm * HH + gn) =
                            make_float2(acc[mb][nb][rh * 2 + 0], acc[mb][nb][rh * 2 + 1]);
                    }
                }
            }
        }
        grid_barrier(bt++);   // all partials of diagonal d visible

        // ---- combine phase: sum 3 partials + bias + tanh + split + store ----
        {
            const int NV = 3 * BH / 4;
            for (int v = cta * NTHR + tid; v < NV; v += GSTRIDE) {
                const int s = v >> 16;           // BH/4 = 65536 per slot
                const int tt = d - s;
                if (tt < 0 || tt >= SS) continue;
                const int i = (v & 65535) * 4;
                const float4 p0 = *(const float4*)&g_part[s][0][i];
                const float4 p1 = *(const float4*)&g_part[s][1][i];
                const float4 p2 = *(const float4*)&g_part[s][2][i];
                const float4 bv = *(const float4*)&g_bias[s][i & 1023];
                float f[4];
                f[0] = ftanh(p0.x + p1.x + p2.x + bv.x);
                f[1] = ftanh(p0.y + p1.y + p2.y + bv.y);
                f[2] = ftanh(p0.z + p1.z + p2.z + bv.z);
                f[3] = ftanh(p0.w + p1.w + p2.w + bv.w);
                ush hu[4], lu[4];
                #pragma unroll
                for (int j = 0; j < 4; j++) split2(f[j], hu[j], lu[j]);
                *(uint2*)&g_h_hi[s][tt & 1][i] =
                    make_uint2((unsigned)hu[0] | ((unsigned)hu[1] << 16),
                               (unsigned)hu[2] | ((unsigned)hu[3] << 16));
                *(uint2*)&g_h_lo[s][tt & 1][i] =
                    make_uint2((unsigned)lu[0] | ((unsigned)lu[1] << 16),
                               (unsigned)lu[2] | ((unsigned)lu[3] << 16));
                if (s == LL - 1)
                    *(float4*)(out + (size_t)tt * BH + i) = make_float4(f[0], f[1], f[2], f[3]);
                if (tt == SS - 1)
                    *(float4*)(out + (size_t)SS * BH + (size_t)s * BH + i) =
                        make_float4(f[0], f[1], f[2], f[3]);
            }
            // split x_{d+1} into the other ring slot
            const int tn = d + 1;
            if (tn < SS) {
                const int sl = tn & 1;
                for (int i = cta * NTHR + tid; i < BH; i += GSTRIDE)
                    split2(x[(size_t)tn * BH + i], g_x_hi[sl][i], g_x_lo[sl][i]);
            }
        }
        grid_barrier(bt++);   // h/x ready for diagonal d+1
    }
}

extern "C" void kernel_launch(void* const* d_in, const int* in_sizes, int n_in,
                              void* d_out, int out_size) {
    const float* x    = (const float*)d_in[0];
    const float* h0   = (const float*)d_in[1];
    const float* W_ih = (const float*)d_in[2];
    const float* W_hh = (const float*)d_in[3];
    const float* b_ih = (const float*)d_in[4];
    const float* b_hh = (const float*)d_in[5];
    float* out = (float*)d_out;

    cudaFuncSetAttribute(rnn_mma, cudaFuncAttributeMaxDynamicSharedMemorySize, SMEM_DYN);
    void* sp = nullptr;
    cudaGetSymbolAddress(&sp, g_sync);
    cudaMemsetAsync(sp, 0, sizeof(unsigned) * 2);
    rnn_mma<<<NCTA, NTHR, SMEM_DYN>>>(x, h0, W_ih, W_hh, b_ih, b_hh, out);
}

// round 16
// speedup vs baseline: 3.1661x; 1.0229x over previous
#include <cuda_runtime.h>
#include <cuda_bf16.h>
#include <stdint.h>
#include <math.h>

#define SS 256
#define BB 256
#define HH 1024
#define LL 3
#define NCTA 144
#define NTHR 256
#define KC 64
#define NCHUNK 32
#define BH (BB*HH)
#define GSTRIDE (NCTA*NTHR)
#define KTOT 2048
#define RSB 144
#define OFF_W 18432
#define BUFSZ 36864
#define NSTAGE 3
#define SMEM_DYN (NSTAGE*BUFSZ + 16)

typedef unsigned short ush;

// ---------------- device state (static scratch; allocation forbidden) --------
__device__ ush g_h_hi[LL][2][BH];
__device__ ush g_h_lo[LL][2][BH];
__device__ ush g_x_hi[2][BH];
__device__ ush g_x_lo[2][BH];
__device__ ush g_w_hi[LL][HH][KTOT];   // [l][n][k2]: k2<1024 W_ih, else W_hh
__device__ ush g_w_lo[LL][HH][KTOT];
__device__ float g_part[LL][3][BH];    // per-stage per-product fp32 partials
__device__ float g_bias[LL][HH];
__device__ unsigned g_sync[2];

// ---------------- helpers ----------------------------------------------------
static __device__ __forceinline__ unsigned smem_u32(const void* p) {
    unsigned a;
    asm("{ .reg .u64 t; cvta.to.shared.u64 t, %1; cvt.u32.u64 %0, t; }" : "=r"(a) : "l"(p));
    return a;
}
static __device__ __forceinline__ ush f2bf(float f) {
    ush r; asm("cvt.rn.bf16.f32 %0, %1;" : "=h"(r) : "f"(f)); return r;
}
static __device__ __forceinline__ void split2(float f, ush& hi, ush& lo) {
    unsigned u = __float_as_uint(f) & 0xFFFF0000u;
    hi = (ush)(u >> 16);
    lo = f2bf(f - __uint_as_float(u));
}
static __device__ __forceinline__ float ftanh(float p) {
    float xc = fminf(fmaxf(p, -15.f), 15.f);
    float e = __expf(2.f * xc);
    return __fdividef(e - 1.f, e + 1.f);
}
static __device__ __forceinline__ void cp16(unsigned s, const void* g) {
    asm volatile("cp.async.cg.shared.global [%0], [%1], 16;" :: "r"(s), "l"(g) : "memory");
}
static __device__ __forceinline__ void cp_commit() {
    asm volatile("cp.async.commit_group;" ::: "memory");
}
static __device__ __forceinline__ void cp_wait1() {
    asm volatile("cp.async.wait_group 1;" ::: "memory");
}
static __device__ __forceinline__ void cp_wait0() {
    asm volatile("cp.async.wait_group 0;" ::: "memory");
}
static __device__ __forceinline__ void ldm_x4(unsigned* r, unsigned a) {
    asm volatile("ldmatrix.sync.aligned.m8n8.x4.shared.b16 {%0,%1,%2,%3}, [%4];"
                 : "=r"(r[0]), "=r"(r[1]), "=r"(r[2]), "=r"(r[3]) : "r"(a));
}
static __device__ __forceinline__ void mma16816(float* c, const unsigned* a, const unsigned* b) {
    asm volatile("mma.sync.aligned.m16n8k16.row.col.f32.bf16.bf16.f32 "
                 "{%0,%1,%2,%3}, {%4,%5,%6,%7}, {%8,%9}, {%0,%1,%2,%3};"
                 : "+f"(c[0]), "+f"(c[1]), "+f"(c[2]), "+f"(c[3])
                 : "r"(a[0]), "r"(a[1]), "r"(a[2]), "r"(a[3]), "r"(b[0]), "r"(b[1]));
}

// sense-free grid barrier; 144 CTAs co-resident
__device__ __forceinline__ void grid_barrier(unsigned target) {
    __syncthreads();
    __threadfence();
    if (threadIdx.x == 0) {
        unsigned old = atomicAdd(&g_sync[0], 1u);
        if (old == NCTA - 1) {
            atomicExch(&g_sync[0], 0u);
            __threadfence();
            atomicExch(&g_sync[1], target);
        } else {
            while (*((volatile unsigned*)&g_sync[1]) < target) { }
        }
        __threadfence();
    }
    __syncthreads();
}

static __device__ __forceinline__ void issue_loads(
    int c, unsigned sbase, int tid, int m0, int n0,
    const ush* inpC, const ush* prvC, const ush* wC)
{
    const int ko = (c & 15) * KC;
    const ush* aC = (c < 16) ? inpC : prvC;
    #pragma unroll
    for (int j = 0; j < 4; j++) {
        int cid = tid + 256 * j;
        int row = cid >> 3, seg = cid & 7;
        cp16(sbase + row * RSB + seg * 16, aC + (size_t)(m0 + row) * HH + ko + seg * 8);
    }
    #pragma unroll
    for (int j = 0; j < 4; j++) {
        int cid = tid + 256 * j;
        int row = cid >> 3, seg = cid & 7;
        cp16(sbase + OFF_W + row * RSB + seg * 16, wC + (size_t)(n0 + row) * KTOT + c * KC + seg * 8);
    }
}

// warp computes its 32x64 sub-tile over one 64-K chunk.
// Fragment double-buffering: kk+1's LDSMs issue BEFORE kk's MMAs so the
// ~29cyc LDSM latency is covered by 16 independent MMAs (2 warps/SMSP suffice).
static __device__ __forceinline__ void compute_chunk(
    unsigned sbase, int lane, int wm, int wn, float acc[2][8][4])
{
    const int arow = lane & 15, akoff = (lane >> 4) * 8;
    unsigned a[2][2][4], b[2][8][2];
    // preload kk = 0
    #pragma unroll
    for (int mb = 0; mb < 2; mb++)
        ldm_x4(a[0][mb], sbase + (wm + mb * 16 + arow) * RSB + akoff * 2);
    #pragma unroll
    for (int g = 0; g < 4; g++) {
        unsigned r[4];
        ldm_x4(r, sbase + OFF_W + (wn + g * 16 + arow) * RSB + akoff * 2);
        b[0][2 * g][0] = r[0]; b[0][2 * g][1] = r[2];
        b[0][2 * g + 1][0] = r[1]; b[0][2 * g + 1][1] = r[3];
    }
    #pragma unroll
    for (int kk = 0; kk < 4; kk++) {
        const int cur = kk & 1, nxt = cur ^ 1;
        if (kk < 3) {
            #pragma unroll
            for (int mb = 0; mb < 2; mb++)
                ldm_x4(a[nxt][mb],
                       sbase + (wm + mb * 16 + arow) * RSB + ((kk + 1) * 16 + akoff) * 2);
            #pragma unroll
            for (int g = 0; g < 4; g++) {
                unsigned r[4];
                ldm_x4(r, sbase + OFF_W + (wn + g * 16 + arow) * RSB + ((kk + 1) * 16 + akoff) * 2);
                b[nxt][2 * g][0] = r[0]; b[nxt][2 * g][1] = r[2];
                b[nxt][2 * g + 1][0] = r[1]; b[nxt][2 * g + 1][1] = r[3];
            }
        }
        #pragma unroll
        for (int mb = 0; mb < 2; mb++)
            #pragma unroll
            for (int nb = 0; nb < 8; nb++)
                mma16816(acc[mb][nb], a[cur][mb], b[cur][nb]);
    }
}

// ---------------- persistent kernel ------------------------------------------
__global__ void __launch_bounds__(NTHR, 1) rnn_mma(
    const float* __restrict__ x, const float* __restrict__ h0,
    const float* __restrict__ W_ih, const float* __restrict__ W_hh,
    const float* __restrict__ b_ih, const float* __restrict__ b_hh,
    float* __restrict__ out)
{
    extern __shared__ __align__(16) char dsm[];

    const int tid = threadIdx.x;
    const int lane = tid & 31;
    const int w = tid >> 5;
    const int wm = (w >> 1) * 32;
    const int wn = (w & 1) * 64;
    const int cta = blockIdx.x;
    const int l = cta / 48;
    const int p = (cta / 16) % 3;        // 0: Ah*Wh 1: Al*Wh 2: Ah*Wl
    const int tile = cta % 16;
    const int m0 = (tile & 1) * 128;
    const int n0 = (tile >> 1) * 128;

    const unsigned dynu = smem_u32(dsm);

    // ---- prepass: split W / h0 / x0, bias sums ------------------------------
    for (int idx = cta * NTHR + tid; idx < LL * HH * KTOT; idx += GSTRIDE) {
        int l2 = idx >> 21;
        int rem = idx & ((1 << 21) - 1);
        int n = rem >> 11;
        int k2 = rem & (KTOT - 1);
        float f = (k2 < HH) ? W_ih[((size_t)l2 * HH + n) * HH + k2]
                            : W_hh[((size_t)l2 * HH + n) * HH + (k2 - HH)];
        split2(f, ((ush*)g_w_hi)[idx], ((ush*)g_w_lo)[idx]);
    }
    for (int idx = cta * NTHR + tid; idx < LL * BH; idx += GSTRIDE) {
        int l2 = idx >> 18;
        int i = idx & (BH - 1);
        split2(h0[idx], g_h_hi[l2][1][i], g_h_lo[l2][1][i]);
    }
    for (int idx = cta * NTHR + tid; idx < BH; idx += GSTRIDE)
        split2(x[idx], g_x_hi[0][idx], g_x_lo[0][idx]);
    for (int idx = cta * NTHR + tid; idx < LL * HH; idx += GSTRIDE)
        ((float*)g_bias)[idx] = b_ih[idx] + b_hh[idx];

    grid_barrier(1u);
    unsigned bt = 2;

    const ush* wC = (p == 2) ? &g_w_lo[l][0][0] : &g_w_hi[l][0][0];

    for (int d = 0; d < SS + LL - 1; d++) {
        const int t = d - l;
        if (t >= 0 && t < SS) {
            const ush* inpC;
            const ush* prvC;
            if (p == 1) {   // A = lo component
                inpC = (l == 0) ? g_x_lo[t & 1] : g_h_lo[l - 1][t & 1];
                prvC = g_h_lo[l][(t & 1) ^ 1];
            } else {        // A = hi component
                inpC = (l == 0) ? g_x_hi[t & 1] : g_h_hi[l - 1][t & 1];
                prvC = g_h_hi[l][(t & 1) ^ 1];
            }

            float acc[2][8][4];
            #pragma unroll
            for (int a = 0; a < 2; a++)
                #pragma unroll
                for (int b = 0; b < 8; b++)
                    #pragma unroll
                    for (int cc = 0; cc < 4; cc++) acc[a][b][cc] = 0.f;

            // 3-stage cp.async ring, one barrier per chunk
            issue_loads(0, dynu + 0 * BUFSZ, tid, m0, n0, inpC, prvC, wC);
            cp_commit();
            issue_loads(1, dynu + 1 * BUFSZ, tid, m0, n0, inpC, prvC, wC);
            cp_commit();
            int bufc = 0;
            for (int c = 0; c < NCHUNK; c++) {
                if (c == NCHUNK - 1) cp_wait0(); else cp_wait1();
                __syncthreads();
                if (c + 2 < NCHUNK) {
                    int bufn = bufc + 2 - ((bufc + 2 >= NSTAGE) ? NSTAGE : 0);
                    issue_loads(c + 2, dynu + bufn * BUFSZ, tid, m0, n0, inpC, prvC, wC);
                    cp_commit();
                }
                compute_chunk(dynu + bufc * BUFSZ, lane, wm, wn, acc);
                if (++bufc == NSTAGE) bufc = 0;
            }

            // write fp32 partial tile to global scratch
            float* pd = &g_part[l][p][0];
            #pragma unroll
            for (int mb = 0; mb < 2; mb++) {
                #pragma unroll
                for (int rh = 0; rh < 2; rh++) {
                    const int gm = m0 + wm + mb * 16 + rh * 8 + (lane >> 2);
                    #pragma unroll
                    for (int nb = 0; nb < 8; nb++) {
                        const int gn = n0 + wn + nb * 8 + 2 * (lane & 3);
                        *(float2*)(pd + (size_t)gm * HH + gn) =
                            make_float2(acc[mb][nb][rh * 2 + 0], acc[mb][nb][rh * 2 + 1]);
                    }
                }
            }
        }
        grid_barrier(bt++);   // all partials of diagonal d visible

        // ---- combine phase: sum 3 partials + bias + tanh + split + store ----
        {
            const int NV = 3 * BH / 4;
            for (int v = cta * NTHR + tid; v < NV; v += GSTRIDE) {
                const int s = v >> 16;           // BH/4 = 65536 per slot
                const int tt = d - s;
                if (tt < 0 || tt >= SS) continue;
                const int i = (v & 65535) * 4;
                const float4 p0 = *(const float4*)&g_part[s][0][i];
                const float4 p1 = *(const float4*)&g_part[s][1][i];
                const float4 p2 = *(const float4*)&g_part[s][2][i];
                const float4 bv = *(const float4*)&g_bias[s][i & 1023];
                float f[4];
                f[0] = ftanh(p0.x + p1.x + p2.x + bv.x);
                f[1] = ftanh(p0.y + p1.y + p2.y + bv.y);
                f[2] = ftanh(p0.z + p1.z + p2.z + bv.z);
                f[3] = ftanh(p0.w + p1.w + p2.w + bv.w);
                ush hu[4], lu[4];
                #pragma unroll
                for (int j = 0; j < 4; j++) split2(f[j], hu[j], lu[j]);
                *(uint2*)&g_h_hi[s][tt & 1][i] =
                    make_uint2((unsigned)hu[0] | ((unsigned)hu[1] << 16),
                               (unsigned)hu[2] | ((unsigned)hu[3] << 16));
                *(uint2*)&g_h_lo[s][tt & 1][i] =
                    make_uint2((unsigned)lu[0] | ((unsigned)lu[1] << 16),
                               (unsigned)lu[2] | ((unsigned)lu[3] << 16));
                if (s == LL - 1)
                    *(float4*)(out + (size_t)tt * BH + i) = make_float4(f[0], f[1], f[2], f[3]);
                if (tt == SS - 1)
                    *(float4*)(out + (size_t)SS * BH + (size_t)s * BH + i) =
                        make_float4(f[0], f[1], f[2], f[3]);
            }
            // split x_{d+1} into the other ring slot
            const int tn = d + 1;
            if (tn < SS) {
                const int sl = tn & 1;
                for (int i = cta * NTHR + tid; i < BH; i += GSTRIDE)
                    split2(x[(size_t)tn * BH + i], g_x_hi[sl][i], g_x_lo[sl][i]);
            }
        }
        grid_barrier(bt++);   // h/x ready for diagonal d+1
    }
}

extern "C" void kernel_launch(void* const* d_in, const int* in_sizes, int n_in,
                              void* d_out, int out_size) {
    const float* x    = (const float*)d_in[0];
    const float* h0   = (const float*)d_in[1];
    const float* W_ih = (const float*)d_in[2];
    const float* W_hh = (const float*)d_in[3];
    const float* b_ih = (const float*)d_in[4];
    const float* b_hh = (const float*)d_in[5];
    float* out = (float*)d_out;

    cudaFuncSetAttribute(rnn_mma, cudaFuncAttributeMaxDynamicSharedMemorySize, SMEM_DYN);
    void* sp = nullptr;
    cudaGetSymbolAddress(&sp, g_sync);
    cudaMemsetAsync(sp, 0, sizeof(unsigned) * 2);
    rnn_mma<<<NCTA, NTHR, SMEM_DYN>>>(x, h0, W_ih, W_hh, b_ih, b_hh, out);
}